// round 17
// baseline (speedup 1.0000x reference)
#include <cuda_runtime.h>
#include <cuda_fp16.h>
#include <cstdint>

constexpr int NB  = 8;
constexpr int CH  = 512;
constexpr int HW  = 4096;
constexpr int HW2 = 2048;
constexpr int CO  = 256;

// ---------------- device scratch ----------------
// q,k,v transposed fp16, contiguous: [q(8) | k(8) | v(8)] each (4096,512)
__device__ __align__(256) __half g_xTh[(size_t)3 * NB * HW * CH];
__device__ __align__(256) __half g_W3h[3 * CO * CH];     // phi | theta | g weights (fp16)
__device__ __align__(256) __half g_Wmh[CH * CO];         // mask weights (fp16)
__device__ __align__(256) __half g_gh [(size_t)NB * CH * HW2];
// pT then tT contiguous: [pT(8) | tT(8)] each (2048,512)
__device__ __align__(256) __half g_ptTh[(size_t)2 * NB * HW2 * CH];
__device__ __align__(256) __half g_Sh [(size_t)NB * HW2 * HW2];  // scores fp16, softmax in-place
__device__ __align__(256) __half g_y3h[(size_t)NB * HW * CO];

// ---------------- helpers ----------------
__device__ __forceinline__ uint32_t s2u(const void* p) {
    uint32_t a;
    asm("{ .reg .u64 t; cvta.to.shared.u64 t, %1; cvt.u32.u64 %0, t; }" : "=r"(a) : "l"(p));
    return a;
}
__device__ __forceinline__ void ldsm4(uint32_t* r, uint32_t addr) {
    asm volatile("ldmatrix.sync.aligned.m8n8.x4.shared.b16 {%0,%1,%2,%3}, [%4];"
                 : "=r"(r[0]), "=r"(r[1]), "=r"(r[2]), "=r"(r[3]) : "r"(addr));
}
__device__ __forceinline__ void mma16816(float* d, const uint32_t* a, uint32_t b0, uint32_t b1) {
    asm volatile("mma.sync.aligned.m16n8k16.row.col.f32.f16.f16.f32 "
                 "{%0,%1,%2,%3}, {%4,%5,%6,%7}, {%8,%9}, {%0,%1,%2,%3};"
                 : "+f"(d[0]), "+f"(d[1]), "+f"(d[2]), "+f"(d[3])
                 : "r"(a[0]), "r"(a[1]), "r"(a[2]), "r"(a[3]), "r"(b0), "r"(b1));
}
__device__ __forceinline__ void cpasync16(uint32_t s, const void* g) {
    asm volatile("cp.async.cg.shared.global [%0], [%1], 16;" :: "r"(s), "l"(g));
}
#define CP_COMMIT() asm volatile("cp.async.commit_group;" ::: "memory")
#define CP_WAIT1()  asm volatile("cp.async.wait_group 1;" ::: "memory")
#define CP_WAIT0()  asm volatile("cp.async.wait_group 0;" ::: "memory")

// BK=64: rows of 128 B (64 fp16), 8 chunks of 16 B, swizzle c ^= (row & 7).
// Stage (32 KB): Ah @0, Bh @16384. 3 stages = 96 KB.
__device__ __forceinline__ void load_stage(uint32_t sbase,
    const __half* pAh, const __half* pBh,
    int Ktot, int kofs, int tid)
{
    const int row = tid >> 1;                 // 0..127
    const int c0 = (tid & 1) * 4;             // 0 or 4
    const long long gofs = (long long)row * Ktot + kofs;
    #pragma unroll
    for (int s = 0; s < 4; s++) {
        const int c = c0 + s;
        const uint32_t soff = row * 128 + ((c ^ (row & 7)) << 4);
        cpasync16(sbase +         soff, pAh + gofs + c * 8);
        cpasync16(sbase + 16384 + soff, pBh + gofs + c * 8);
    }
}

// ---------------------------------------------------------------------------
// fp16 tensor-core GEMM (mma.sync), BK=64, 3-stage cp.async pipeline, 1-term.
// D(128x128 fp32 tile) = Ah(MxK) @ Bh^T(NxK), fp16 K-major.
// EPI: 0 row-major fp16 store (scores -> Sh)
//      2 fp32 + r1 + r2 residual (mask)
//      4 transposed hi store, parity-grouped cols (apply -> y3)
//      6 TRIPLE conv: z = 0..23, sel = z>>3. A = W3 + sel*CO*CH.
//        sel<2: transposed hi store (pT/tT). sel==2: row-major hi store to G.
// ---------------------------------------------------------------------------
template <int EPI>
__global__ void __launch_bounds__(256, 2) mma_gemm(
    const __half* __restrict__ Ah, const __half* __restrict__ Bh,
    float* __restrict__ C, __half* __restrict__ Ch, __half* __restrict__ G,
    int Ktot, int ldc,
    long long sA, long long sB, long long sC,
    const float* __restrict__ r1, const float* __restrict__ r2)
{
    extern __shared__ __align__(1024) char sm[];
    const int tid = threadIdx.x;
    const int wid = tid >> 5, lane = tid & 31;
    const uint32_t sb = s2u(sm);

    const int m0 = blockIdx.y * 128;
    const int n0 = blockIdx.x * 128;
    const long long bz = blockIdx.z;
    const int sel = (EPI == 6) ? (int)(bz >> 3) : 0;

    const __half* pAh = Ah + bz * sA + (long long)sel * CO * CH + (long long)m0 * Ktot;
    const __half* pBh = Bh + bz * sB + (long long)n0 * Ktot;

    const int wm = (wid >> 1) * 32;
    const int wn = (wid & 1) * 64;

    float acc[2][8][4];
    #pragma unroll
    for (int i = 0; i < 2; i++)
        #pragma unroll
        for (int j = 0; j < 8; j++)
            #pragma unroll
            for (int t = 0; t < 4; t++) acc[i][j][t] = 0.0f;

    const int nch = Ktot >> 6;
    load_stage(sb, pAh, pBh, Ktot, 0, tid);
    CP_COMMIT();
    load_stage(sb + 32768, pAh, pBh, Ktot, 64, tid);
    CP_COMMIT();

    uint32_t stage = 0;
    uint32_t nstage = 2;
    for (int ic = 0; ic < nch; ic++) {
        CP_WAIT1();
        __syncthreads();
        if (ic + 2 < nch) {
            load_stage(sb + nstage * 32768, pAh, pBh, Ktot, (ic + 2) << 6, tid);
        }
        CP_COMMIT();
        nstage = (nstage == 2) ? 0 : nstage + 1;

        const uint32_t st = sb + stage * 32768;
        stage = (stage == 2) ? 0 : stage + 1;
        #pragma unroll
        for (int kk = 0; kk < 64; kk += 16) {
            const int kc = (kk >> 3) + (lane >> 4);   // 0..7
            uint32_t a_h[2][4], b_all[4][4];
            #pragma unroll
            for (int mi = 0; mi < 2; mi++) {
                const int row = wm + mi * 16 + (lane & 15);
                const uint32_t ad = st + row * 128 + ((kc ^ (row & 7)) << 4);
                ldsm4(a_h[mi], ad);
            }
            #pragma unroll
            for (int jj = 0; jj < 4; jj++) {
                const int row = wn + jj * 16 + (lane & 15);
                const uint32_t bd = st + 16384 + row * 128 + ((kc ^ (row & 7)) << 4);
                ldsm4(b_all[jj], bd);
            }
            #pragma unroll
            for (int jj = 0; jj < 4; jj++)
                #pragma unroll
                for (int mi = 0; mi < 2; mi++) {
                    mma16816(acc[mi][jj * 2],     a_h[mi], b_all[jj][0], b_all[jj][2]);
                    mma16816(acc[mi][jj * 2 + 1], a_h[mi], b_all[jj][1], b_all[jj][3]);
                }
        }
    }

    const int g = lane >> 2, tg = lane & 3;

    if (EPI == 6 && sel == 2) {
        // g conv: row-major hi store, ld = HW, batch stride = CO*HW
        const long long gbz = (bz - 16) * (long long)CO * HW;
        #pragma unroll
        for (int mi = 0; mi < 2; mi++)
            #pragma unroll
            for (int j = 0; j < 8; j++) {
                const int row = m0 + wm + mi * 16 + g;
                const int col = n0 + wn + j * 8 + tg * 2;
                #pragma unroll
                for (int h = 0; h < 2; h++) {
                    const long long idx = gbz + (long long)(row + h * 8) * HW + col;
                    *(__half2*)(G + idx) = __halves2half2(
                        __float2half(acc[mi][j][h * 2]), __float2half(acc[mi][j][h * 2 + 1]));
                }
            }
        return;
    }

    const long long cbz = bz * sC;

    if (EPI == 6 || EPI == 4) {
        // stage tile fp32 in smem [row(m) * 129 + col(n)], transposed coalesced stores
        CP_WAIT0();
        __syncthreads();
        float* Dsm = (float*)sm;
        #pragma unroll
        for (int mi = 0; mi < 2; mi++)
            #pragma unroll
            for (int j = 0; j < 8; j++)
                #pragma unroll
                for (int h = 0; h < 2; h++) {
                    const int row = wm + mi * 16 + g + h * 8;
                    const int col = wn + j * 8 + tg * 2;
                    Dsm[row * 129 + col]     = acc[mi][j][h * 2];
                    Dsm[row * 129 + col + 1] = acc[mi][j][h * 2 + 1];
                }
        __syncthreads();

        if (EPI == 6) {
            // pT/tT: out[n][h1*256 + o]; row = 128 fp16 = 256B = 16 lanes x 16B.
            const int h1 = n0 >> 11;
            const int xb = n0 & 2047;
            const int lane16 = lane & 15;
            const int sub = lane >> 4;                 // 2 rows per warp per pass
            #pragma unroll
            for (int p = 0; p < 8; p++) {
                const int n_loc = p * 16 + wid * 2 + sub;
                __align__(16) __half hbuf[8];
                #pragma unroll
                for (int j = 0; j < 8; j++)
                    hbuf[j] = __float2half(Dsm[(lane16 * 8 + j) * 129 + n_loc]);
                const long long ob = cbz + (long long)(xb + n_loc) * ldc
                                   + h1 * 256 + m0 + lane16 * 8;
                *(uint4*)(Ch + ob) = *(uint4*)hbuf;
            }
        } else {
            // y3[h1*2048 + n0 + m][m0/2 + o2]; row = 64 fp16 = 128B = 8 lanes x 16B.
            const int lane8 = lane & 7;
            const int rsub = lane >> 3;                // 4 rows per warp per pass
            #pragma unroll
            for (int p = 0; p < 8; p++) {
                const int R = p * 32 + wid * 4 + rsub; // 0..255
                const int h1 = R >> 7;
                const int m_loc = R & 127;
                __align__(16) __half hbuf[8];
                #pragma unroll
                for (int j = 0; j < 8; j++)
                    hbuf[j] = __float2half(Dsm[(2 * (lane8 * 8 + j) + h1) * 129 + m_loc]);
                const long long ob = cbz + (long long)(h1 * 2048 + n0 + m_loc) * ldc
                                   + (m0 >> 1) + lane8 * 8;
                *(uint4*)(Ch + ob) = *(uint4*)hbuf;
            }
        }
        return;
    }

    // direct epilogues: 0 = fp16 row-major (scores), 2 = fp32 + residuals (mask)
    #pragma unroll
    for (int mi = 0; mi < 2; mi++) {
        #pragma unroll
        for (int j = 0; j < 8; j++) {
            const int row = m0 + wm + mi * 16 + g;
            const int col = n0 + wn + j * 8 + tg * 2;
            #pragma unroll
            for (int h = 0; h < 2; h++) {
                const long long idx = cbz + (long long)(row + h * 8) * ldc + col;
                const float d0 = acc[mi][j][h * 2];
                const float d1 = acc[mi][j][h * 2 + 1];
                if (EPI == 0) {
                    *(__half2*)(Ch + idx) =
                        __halves2half2(__float2half(d0), __float2half(d1));
                } else {
                    const float2 a = *(const float2*)(r1 + idx);
                    const float2 b = *(const float2*)(r2 + idx);
                    *(float2*)(C + idx) = make_float2(d0 + a.x + b.x, d1 + a.y + b.y);
                }
            }
        }
    }
}

// ---------------------------------------------------------------------------
// conversion kernels
// ---------------------------------------------------------------------------
// fp32 -> fp16 for all 4 weight tensors (one launch)
__global__ void __launch_bounds__(256) wconv_kernel(
    const float* __restrict__ s0, const float* __restrict__ s1,
    const float* __restrict__ s2, const float* __restrict__ s3,
    __half* __restrict__ w3h, __half* __restrict__ wmh)
{
    const int i = blockIdx.x * 256 + threadIdx.x;
    const int wsel = blockIdx.y;
    const float* s = (wsel == 0) ? s0 : (wsel == 1) ? s1 : (wsel == 2) ? s2 : s3;
    __half* dst = (wsel == 3) ? wmh : (w3h + wsel * CO * CH);
    dst[i] = __float2half(s[i]);
}

// q,k,v: (b,512,4096) -> (b,4096,512) fp16, z = 0..23. half2 stores.
__global__ void __launch_bounds__(256) tconv3_kernel(const float* __restrict__ q,
                                                     const float* __restrict__ k,
                                                     const float* __restrict__ v,
                                                     __half* __restrict__ oh) {
    __shared__ float T[64][33];
    const int z = blockIdx.z;
    const int b = z & 7;
    const float* src = (z < NB) ? q : (z < 2 * NB) ? k : v;
    const float* I = src + (size_t)b * CH * HW;
    const int tx = threadIdx.x & 31, ty = threadIdx.x >> 5;
    const int x0 = blockIdx.x * 32, c0 = blockIdx.y * 64;
    #pragma unroll
    for (int r = 0; r < 8; r++) {
        const int cl = r * 8 + ty;
        T[cl][tx] = I[(size_t)(c0 + cl) * HW + x0 + tx];
    }
    __syncthreads();
    const size_t ob = (size_t)z * HW * CH;
    #pragma unroll
    for (int p = 0; p < 4; p++) {
        const int xl = p * 8 + ty;
        const __half2 val = __halves2half2(__float2half(T[2 * tx][xl]),
                                           __float2half(T[2 * tx + 1][xl]));
        *(__half2*)(oh + ob + (size_t)(x0 + xl) * CH + c0 + 2 * tx) = val;
    }
}

// in-place row softmax on fp16 scores (rows of length 2048)
__global__ void __launch_bounds__(256) softmax_h_kernel(__half* __restrict__ Sh) {
    const size_t row = blockIdx.x;
    uint4* p = (uint4*)(Sh + row * HW2);
    const int tid = threadIdx.x;

    uint4 raw = p[tid];                      // 8 fp16
    __half2 h[4];
    h[0] = *(__half2*)&raw.x; h[1] = *(__half2*)&raw.y;
    h[2] = *(__half2*)&raw.z; h[3] = *(__half2*)&raw.w;
    float vf[8];
    #pragma unroll
    for (int i = 0; i < 4; i++) {
        const float2 f = __half22float2(h[i]);
        vf[2 * i] = f.x; vf[2 * i + 1] = f.y;
    }

    float mx = vf[0];
    #pragma unroll
    for (int i = 1; i < 8; i++) mx = fmaxf(mx, vf[i]);
    __shared__ float red[8];
    #pragma unroll
    for (int o = 16; o > 0; o >>= 1) mx = fmaxf(mx, __shfl_xor_sync(0xffffffffu, mx, o));
    if ((tid & 31) == 0) red[tid >> 5] = mx;
    __syncthreads();
    mx = red[0];
    #pragma unroll
    for (int i = 1; i < 8; i++) mx = fmaxf(mx, red[i]);
    __syncthreads();

    float sum = 0.0f;
    #pragma unroll
    for (int i = 0; i < 8; i++) { vf[i] = __expf(vf[i] - mx); sum += vf[i]; }
    #pragma unroll
    for (int o = 16; o > 0; o >>= 1) sum += __shfl_xor_sync(0xffffffffu, sum, o);
    if ((tid & 31) == 0) red[tid >> 5] = sum;
    __syncthreads();
    sum = red[0];
    #pragma unroll
    for (int i = 1; i < 8; i++) sum += red[i];

    const float inv = 1.0f / sum;
    #pragma unroll
    for (int i = 0; i < 4; i++)
        h[i] = __halves2half2(__float2half(vf[2 * i] * inv), __float2half(vf[2 * i + 1] * inv));
    raw.x = *(uint32_t*)&h[0]; raw.y = *(uint32_t*)&h[1];
    raw.z = *(uint32_t*)&h[2]; raw.w = *(uint32_t*)&h[3];
    p[tid] = raw;
}

// ---------------------------------------------------------------------------
extern "C" void kernel_launch(void* const* d_in, const int* in_sizes, int n_in,
                              void* d_out, int out_size)
{
    const float* q    = (const float*)d_in[0];
    const float* k    = (const float*)d_in[1];
    const float* v    = (const float*)d_in[2];
    const float* Wphi = (const float*)d_in[3];
    const float* Wth  = (const float*)d_in[4];
    const float* Wg   = (const float*)d_in[5];
    const float* Wm   = (const float*)d_in[6];
    float* out = (float*)d_out;

    // 3 x 32 KB stages = 96 KB; epilogue Dsm (66048 B) fits inside
    constexpr int SMEM = 98304;
    cudaFuncSetAttribute(mma_gemm<6>, cudaFuncAttributeMaxDynamicSharedMemorySize, SMEM);
    cudaFuncSetAttribute(mma_gemm<0>, cudaFuncAttributeMaxDynamicSharedMemorySize, SMEM);
    cudaFuncSetAttribute(mma_gemm<4>, cudaFuncAttributeMaxDynamicSharedMemorySize, SMEM);
    cudaFuncSetAttribute(mma_gemm<2>, cudaFuncAttributeMaxDynamicSharedMemorySize, SMEM);

    __half *xTh, *W3h, *Wmh, *gh, *ptTh, *Sh, *y3h;
    cudaGetSymbolAddress((void**)&xTh, g_xTh);
    cudaGetSymbolAddress((void**)&W3h, g_W3h);
    cudaGetSymbolAddress((void**)&Wmh, g_Wmh);
    cudaGetSymbolAddress((void**)&gh, g_gh);
    cudaGetSymbolAddress((void**)&ptTh, g_ptTh);
    cudaGetSymbolAddress((void**)&Sh, g_Sh);
    cudaGetSymbolAddress((void**)&y3h, g_y3h);

    const dim3 blk(256);
    const long long sX  = (long long)CH * HW;    // q/k/v/out batch stride
    const long long sT  = (long long)HW * CH;    // xT per-z stride
    const long long sP  = (long long)CO * HW;    // g
    const long long sPT = (long long)HW2 * CH;   // pT/tT per-z stride
    const long long sS  = (long long)HW2 * HW2;  // scores
    const long long sY3 = (long long)HW * CO;    // y3

    __half* tTh = ptTh + (size_t)NB * sPT;

    // 0) weight conversions (one launch)
    wconv_kernel<<<dim3(CO * CH / 256, 4), blk>>>(Wphi, Wth, Wg, Wm, W3h, Wmh);

    // 1) q/k/v transposes -> fp16 (one launch)
    tconv3_kernel<<<dim3(HW / 32, CH / 64, 3 * NB), blk>>>(q, k, v, xTh);

    // 2) TRIPLE conv (1-term): phi -> pT | theta -> tT | g -> row-major
    mma_gemm<6><<<dim3(HW / 128, CO / 128, 3 * NB), blk, SMEM>>>(
        W3h, xTh, nullptr, ptTh, gh,
        CH, CH, 0, sT, sPT, nullptr, nullptr);

    // 3) scores (1-term) -> fp16 Sh directly
    mma_gemm<0><<<dim3(HW2 / 128, HW2 / 128, NB), blk, SMEM>>>(
        ptTh, tTh, nullptr, Sh, nullptr,
        CH, HW2, sPT, sPT, sS, nullptr, nullptr);

    // 4) in-place row softmax on fp16
    softmax_h_kernel<<<NB * HW2, blk>>>(Sh);

    // 5) attn apply (1-term, EPI=4): writes y3h transposed directly
    mma_gemm<4><<<dim3(HW2 / 128, CH / 128, NB), blk, SMEM>>>(
        gh, Sh, nullptr, y3h, nullptr,
        HW2, CO, sP, sS, sY3, nullptr, nullptr);

    // 6) mask conv (1-term) + residual: out = Wm @ y3 + q + v
    mma_gemm<2><<<dim3(HW / 128, CH / 128, NB), blk, SMEM>>>(
        Wmh, y3h, out, nullptr, nullptr,
        CO, HW, 0, sY3, sX, q, v);
}